// round 7
// baseline (speedup 1.0000x reference)
#include <cuda_runtime.h>
#include <cstdint>

#define PS 32
#define NB 36
#define WPB 8                    // warps per block
#define PPW 2                    // patches per warp
#define THREADS (WPB * 32)

// fp32 constants exactly as XLA materializes them
#define PI_F     3.14159274101257324219f   // (float)pi
#define TWOPI_F  6.28318548202514648438f   // (float)(2*pi)

// One pixel: exact reference fp32 op order (no fma contraction).
__device__ __forceinline__ void pixel(float cur, float up, float dn, float g,
                                      float* __restrict__ h) {
    const float lft = __shfl_up_sync(0xffffffffu, cur, 1);   // OOR -> own value = replicate
    const float rgt = __shfl_down_sync(0xffffffffu, cur, 1);
    const float gx = __fmul_rn(0.5f, __fsub_rn(lft, rgt));
    const float gy = __fmul_rn(0.5f, __fsub_rn(up, dn));
    const float s2 = __fadd_rn(__fadd_rn(__fmul_rn(gx, gx), __fmul_rn(gy, gy)), 1e-10f);
    const float mag = __fmul_rn(sqrtf(s2), g);
    const float ori = atan2f(gy, gx);
    // o_big = (36 * (ori + pi)) / (2*pi)
    const float o  = __fdiv_rn(__fmul_rn(36.0f, __fadd_rn(ori, PI_F)), TWOPI_F);
    const float bo = floorf(o);
    const float w  = __fmul_rn(__fsub_rn(1.0f, __fsub_rn(o, bo)), mag);
    int ib = (int)bo;
    if (ib >= NB) ib -= NB;      // only o==36 wraps (ori==+pi)
    atomicAdd(&h[ib], w);
}

// Smooth (0.33,0.34,0.33) zero-padded + first-max argmax + angle, warp-parallel.
__device__ __forceinline__ void epilogue(const float* __restrict__ h, int lane,
                                         float* __restrict__ out, int b) {
    const float c0 = h[lane];
    const float l0 = (lane > 0) ? h[lane - 1] : 0.0f;
    const float r0 = h[lane + 1];             // lane 31 -> h[32] (real neighbor)
    float bv = __fadd_rn(__fadd_rn(__fmul_rn(0.33f, l0), __fmul_rn(0.34f, c0)),
                         __fmul_rn(0.33f, r0));
    int bi = lane;
    if (lane < NB - 32) {                     // lanes 0..3 handle bins 32..35
        const int i2 = lane + 32;
        const float c2 = h[i2];
        const float l2 = h[i2 - 1];
        const float r2 = (i2 < NB - 1) ? h[i2 + 1] : 0.0f;
        const float s2 = __fadd_rn(__fadd_rn(__fmul_rn(0.33f, l2), __fmul_rn(0.34f, c2)),
                                   __fmul_rn(0.33f, r2));
        if (s2 > bv) { bv = s2; bi = i2; }    // i2 > lane: tie keeps lane (first-max)
    }
    #pragma unroll
    for (int off = 16; off > 0; off >>= 1) {
        const float ov = __shfl_xor_sync(0xffffffffu, bv, off);
        const int   oi = __shfl_xor_sync(0xffffffffu, bi, off);
        if (ov > bv || (ov == bv && oi < bi)) { bv = ov; bi = oi; }
    }
    if (lane == 0)
        out[b] = -__fsub_rn(__fdiv_rn(__fmul_rn(TWOPI_F, (float)bi), 36.0f), PI_F);
}

__global__ __launch_bounds__(THREADS)
void orient_kernel(const float* __restrict__ x,
                   const float* __restrict__ gk,
                   float* __restrict__ out, int B) {
    __shared__ float hist[WPB * PPW][NB];

    const int warp = threadIdx.x >> 5;
    const int lane = threadIdx.x & 31;
    const int b0 = (blockIdx.x * WPB + warp) * PPW;
    if (b0 >= B) return;                      // warp-independent: no block syncs
    const bool has2 = (b0 + 1 < B);

    float* __restrict__ h0 = hist[warp * PPW + 0];
    float* __restrict__ h1 = hist[warp * PPW + 1];
    h0[lane] = 0.0f; h1[lane] = 0.0f;
    if (lane < NB - 32) { h0[lane + 32] = 0.0f; h1[lane + 32] = 0.0f; }
    __syncwarp();

    const float* p0 = x + (size_t)b0 * (PS * PS) + lane;
    const float* p1 = has2 ? (p0 + PS * PS) : p0;   // clamp: harmless duplicate work
    const float* pg = gk + lane;

    // Two rolling 4-register row buffers, one per patch.
    float a[4], c[4];
    a[0] = __ldg(p0);           c[0] = __ldg(p1);
    a[1] = __ldg(p0 + PS);      c[1] = __ldg(p1 + PS);
    a[2] = __ldg(p0 + 2 * PS);  c[2] = __ldg(p1 + 2 * PS);
    a[3] = a[0];                c[3] = c[0];            // "row -1" = row 0

    #pragma unroll 4
    for (int r = 0; r < PS; r++) {
        const int pr = (r + 2 < PS) ? (r + 2) : (PS - 1);
        const float n0 = __ldg(p0 + pr * PS);
        const float n1 = __ldg(p1 + pr * PS);
        const float g  = __ldg(pg + r * PS);            // shared by both patches

        pixel(a[r & 3], a[(r + 3) & 3], a[(r + 1) & 3], g, h0);
        pixel(c[r & 3], c[(r + 3) & 3], c[(r + 1) & 3], g, h1);

        a[(r + 2) & 3] = n0;
        c[(r + 2) & 3] = n1;
    }
    __syncwarp();

    epilogue(h0, lane, out, b0);
    if (has2) epilogue(h1, lane, out, b0 + 1);
}

extern "C" void kernel_launch(void* const* d_in, const int* in_sizes, int n_in,
                              void* d_out, int out_size) {
    const float* x  = (const float*)d_in[0];
    const float* gk = (const float*)d_in[1];
    float* out = (float*)d_out;
    const int B = in_sizes[0] / (PS * PS);
    const int patches_per_block = WPB * PPW;
    const int grid = (B + patches_per_block - 1) / patches_per_block;
    orient_kernel<<<grid, THREADS>>>(x, gk, out, B);
}

// round 8
// speedup vs baseline: 1.0682x; 1.0682x over previous
#include <cuda_runtime.h>
#include <cstdint>

#define PS 32
#define NB 36
#define WPB 4                    // warps (patches) per block
#define THREADS (WPB * 32)

// fp32 constants exactly as XLA materializes them
#define PI_F     3.14159274101257324219f   // (float)pi
#define TWOPI_F  6.28318548202514648438f   // (float)(2*pi)

__global__ __launch_bounds__(THREADS, 16)
void orient_kernel(const float* __restrict__ x,
                   const float* __restrict__ gk,
                   float* __restrict__ out, int B) {
    __shared__ float hist[WPB][NB];

    const int warp = threadIdx.x >> 5;
    const int lane = threadIdx.x & 31;
    const int b = blockIdx.x * WPB + warp;
    if (b >= B) return;               // warp-independent: safe (no block syncs)

    float* __restrict__ h = hist[warp];
    h[lane] = 0.0f;
    if (lane < NB - 32) h[lane + 32] = 0.0f;
    __syncwarp();

    const float* px = x + (size_t)b * (PS * PS) + lane;
    const float* pg = gk + lane;

    // Rolling 4-register row buffer. Invariant entering iter r:
    //   buf[(r+3)&3] = row r-1 (clamped), buf[r&3] = row r, buf[(r+1)&3] = row r+1 (clamped)
    float buf[4];
    buf[0] = __ldg(px);               // row 0
    buf[1] = __ldg(px + PS);          // row 1
    buf[2] = __ldg(px + 2 * PS);      // row 2
    buf[3] = buf[0];                  // "row -1" = row 0 (replicate) for r=0

    // Full unroll: all offsets/indices become immediates (no per-row address math).
    #pragma unroll
    for (int r = 0; r < PS; r++) {
        const int pr = (r + 2 < PS) ? (r + 2) : (PS - 1);   // compile-time constant
        const float nxt = __ldg(px + pr * PS);
        const float g   = __ldg(pg + r * PS);

        const float cur = buf[r & 3];
        const float up  = buf[(r + 3) & 3];   // row r-1 (or clamp)
        const float dn  = buf[(r + 1) & 3];   // row r+1 (or clamp)

        // shfl out-of-range returns own value => replicate clamp for free
        const float lft = __shfl_up_sync(0xffffffffu, cur, 1);
        const float rgt = __shfl_down_sync(0xffffffffu, cur, 1);

        // Exact reference fp32 op order (no fma contraction)
        const float gx = __fmul_rn(0.5f, __fsub_rn(lft, rgt));
        const float gy = __fmul_rn(0.5f, __fsub_rn(up, dn));
        const float s2 = __fadd_rn(__fadd_rn(__fmul_rn(gx, gx), __fmul_rn(gy, gy)), 1e-10f);
        const float mag = __fmul_rn(sqrtf(s2), g);
        const float ori = atan2f(gy, gx);

        // o_big = (36 * (ori + pi)) / (2*pi)
        const float o  = __fdiv_rn(__fmul_rn(36.0f, __fadd_rn(ori, PI_F)), TWOPI_F);
        const float bo = floorf(o);
        const float w  = __fmul_rn(__fsub_rn(1.0f, __fsub_rn(o, bo)), mag);

        int ib = (int)bo;
        if (ib >= NB) ib -= NB;       // only o==36 wraps (ori==+pi)
        atomicAdd(&h[ib], w);

        buf[(r + 2) & 3] = nxt;       // rotate after all reads of this iter
    }
    __syncwarp();

    // Smooth (0.33, 0.34, 0.33), zero-padded; first-max argmax over 36 bins,
    // parallel across the warp. Skipping /1024 is exactly argmax-equivalent.
    const float c0 = h[lane];
    const float l0 = (lane > 0) ? h[lane - 1] : 0.0f;
    const float r0 = h[lane + 1];     // lane 31 -> h[32] (real neighbor, not pad)
    float bv = __fadd_rn(__fadd_rn(__fmul_rn(0.33f, l0), __fmul_rn(0.34f, c0)),
                         __fmul_rn(0.33f, r0));
    int bi = lane;
    if (lane < NB - 32) {             // lanes 0..3 also handle bins 32..35
        const int i2 = lane + 32;
        const float c2 = h[i2];
        const float l2 = h[i2 - 1];
        const float r2 = (i2 < NB - 1) ? h[i2 + 1] : 0.0f;
        const float sm2 = __fadd_rn(__fadd_rn(__fmul_rn(0.33f, l2), __fmul_rn(0.34f, c2)),
                                    __fmul_rn(0.33f, r2));
        if (sm2 > bv) { bv = sm2; bi = i2; }  // i2 > lane: tie keeps lane (first-max)
    }
    #pragma unroll
    for (int off = 16; off > 0; off >>= 1) {
        const float ov = __shfl_xor_sync(0xffffffffu, bv, off);
        const int   oi = __shfl_xor_sync(0xffffffffu, bi, off);
        if (ov > bv || (ov == bv && oi < bi)) { bv = ov; bi = oi; }
    }

    if (lane == 0) {
        // angle = -((2*pi*idx)/36 - pi), exact ref op order
        out[b] = -__fsub_rn(__fdiv_rn(__fmul_rn(TWOPI_F, (float)bi), 36.0f), PI_F);
    }
}

extern "C" void kernel_launch(void* const* d_in, const int* in_sizes, int n_in,
                              void* d_out, int out_size) {
    const float* x  = (const float*)d_in[0];
    const float* gk = (const float*)d_in[1];
    float* out = (float*)d_out;
    const int B = in_sizes[0] / (PS * PS);
    const int grid = (B + WPB - 1) / WPB;
    orient_kernel<<<grid, THREADS>>>(x, gk, out, B);
}

// round 9
// speedup vs baseline: 1.1720x; 1.0971x over previous
#include <cuda_runtime.h>
#include <cstdint>

#define PS 32
#define NB 36
#define WPB 8                    // warps (patches) per block
#define THREADS (WPB * 32)

// fp32 constants exactly as XLA materializes them
#define PI_F     3.14159274101257324219f   // (float)pi
#define TWOPI_F  6.28318548202514648438f   // (float)(2*pi)
#define INV_TWOPI (1.0f / TWOPI_F)         // compile-time RN reciprocal

__global__ __launch_bounds__(THREADS)
void orient_kernel(const float* __restrict__ x,
                   const float* __restrict__ gk,
                   float* __restrict__ out, int B) {
    __shared__ float hist[WPB][NB];

    const int warp = threadIdx.x >> 5;
    const int lane = threadIdx.x & 31;
    const int b = blockIdx.x * WPB + warp;
    if (b >= B) return;               // warp-independent: safe (no block syncs)

    float* __restrict__ h = hist[warp];
    h[lane] = 0.0f;
    if (lane < NB - 32) h[lane + 32] = 0.0f;
    __syncwarp();

    const float* px = x + (size_t)b * (PS * PS) + lane;
    const float* pg = gk + lane;

    // Rolling 4-register row buffer. Invariant entering iter r:
    //   buf[(r+3)&3] = row r-1 (clamped), buf[r&3] = row r, buf[(r+1)&3] = row r+1 (clamped)
    float buf[4];
    buf[0] = __ldg(px);               // row 0
    buf[1] = __ldg(px + PS);          // row 1
    buf[2] = __ldg(px + 2 * PS);      // row 2
    buf[3] = buf[0];                  // "row -1" = row 0 (replicate) for r=0

    #pragma unroll 4
    for (int r = 0; r < PS; r++) {
        // Prefetch row r+2 (clamped) — consumed at iteration r+1.
        const int pr = (r + 2 < PS) ? (r + 2) : (PS - 1);
        const float nxt = __ldg(px + pr * PS);
        const float g   = __ldg(pg + r * PS);

        const float cur = buf[r & 3];
        const float up  = buf[(r + 3) & 3];   // row r-1 (or clamp)
        const float dn  = buf[(r + 1) & 3];   // row r+1 (or clamp)

        // shfl out-of-range returns own value => replicate clamp for free
        const float lft = __shfl_up_sync(0xffffffffu, cur, 1);
        const float rgt = __shfl_down_sync(0xffffffffu, cur, 1);

        // Exact reference fp32 op order (no fma contraction)
        const float gx = __fmul_rn(0.5f, __fsub_rn(lft, rgt));
        const float gy = __fmul_rn(0.5f, __fsub_rn(up, dn));
        const float s2 = __fadd_rn(__fadd_rn(__fmul_rn(gx, gx), __fmul_rn(gy, gy)), 1e-10f);
        const float mag = __fmul_rn(sqrtf(s2), g);
        const float ori = atan2f(gy, gx);

        // o = (36 * (ori + pi)) / (2*pi), correctly-rounded constant division
        // via Markstein: q0 = num*r; e = fma(-c, q0, num); o = fma(e, r, q0).
        const float num = __fmul_rn(36.0f, __fadd_rn(ori, PI_F));
        const float q0  = __fmul_rn(num, INV_TWOPI);
        const float e   = __fmaf_rn(-TWOPI_F, q0, num);
        const float o   = __fmaf_rn(e, INV_TWOPI, q0);

        const float bo = floorf(o);
        const float w  = __fmul_rn(__fsub_rn(1.0f, __fsub_rn(o, bo)), mag);

        int ib = (int)bo;
        if (ib >= NB) ib -= NB;       // only o==36 wraps (ori==+pi)
        atomicAdd(&h[ib], w);

        buf[(r + 2) & 3] = nxt;       // rotate after all reads of this iter
    }
    __syncwarp();

    // Smooth (0.33, 0.34, 0.33), zero-padded; first-max argmax over 36 bins,
    // parallel across the warp. Skipping /1024 is exactly argmax-equivalent.
    const float c0 = h[lane];
    const float l0 = (lane > 0) ? h[lane - 1] : 0.0f;
    const float r0 = h[lane + 1];     // lane 31 -> h[32] (real neighbor, not pad)
    float bv = __fadd_rn(__fadd_rn(__fmul_rn(0.33f, l0), __fmul_rn(0.34f, c0)),
                         __fmul_rn(0.33f, r0));
    int bi = lane;
    if (lane < NB - 32) {             // lanes 0..3 also handle bins 32..35
        const int i2 = lane + 32;
        const float c2 = h[i2];
        const float l2 = h[i2 - 1];
        const float r2 = (i2 < NB - 1) ? h[i2 + 1] : 0.0f;
        const float sm2 = __fadd_rn(__fadd_rn(__fmul_rn(0.33f, l2), __fmul_rn(0.34f, c2)),
                                    __fmul_rn(0.33f, r2));
        if (sm2 > bv) { bv = sm2; bi = i2; }  // i2 > lane: tie keeps lane (first-max)
    }
    #pragma unroll
    for (int off = 16; off > 0; off >>= 1) {
        const float ov = __shfl_xor_sync(0xffffffffu, bv, off);
        const int   oi = __shfl_xor_sync(0xffffffffu, bi, off);
        if (ov > bv || (ov == bv && oi < bi)) { bv = ov; bi = oi; }
    }

    if (lane == 0) {
        // angle = -((2*pi*idx)/36 - pi), exact ref op order
        out[b] = -__fsub_rn(__fdiv_rn(__fmul_rn(TWOPI_F, (float)bi), 36.0f), PI_F);
    }
}

extern "C" void kernel_launch(void* const* d_in, const int* in_sizes, int n_in,
                              void* d_out, int out_size) {
    const float* x  = (const float*)d_in[0];
    const float* gk = (const float*)d_in[1];
    float* out = (float*)d_out;
    const int B = in_sizes[0] / (PS * PS);
    const int grid = (B + WPB - 1) / WPB;
    orient_kernel<<<grid, THREADS>>>(x, gk, out, B);
}

// round 10
// speedup vs baseline: 1.2674x; 1.0814x over previous
#include <cuda_runtime.h>
#include <cstdint>

#define PS 32
#define NB 36
#define WPB 8                     // warps per block
#define PPW 4                     // patches per warp (8 lanes each)
#define THREADS (WPB * 32)

// fp32 constants exactly as XLA materializes them
#define PI_F     3.14159274101257324219f   // (float)pi
#define TWOPI_F  6.28318548202514648438f   // (float)(2*pi)
#define INV_TWOPI (1.0f / TWOPI_F)         // compile-time RN reciprocal

// One pixel: exact reference fp32 op order (no fma contraction).
__device__ __forceinline__ void pixel(float lft, float rgt, float up, float dn,
                                      float g, float* __restrict__ h) {
    const float gx = __fmul_rn(0.5f, __fsub_rn(lft, rgt));
    const float gy = __fmul_rn(0.5f, __fsub_rn(up, dn));
    const float s2 = __fadd_rn(__fadd_rn(__fmul_rn(gx, gx), __fmul_rn(gy, gy)), 1e-10f);
    const float mag = __fmul_rn(sqrtf(s2), g);
    const float ori = atan2f(gy, gx);
    // o = (36*(ori+pi))/(2pi), correctly-rounded constant division (Markstein)
    const float num = __fmul_rn(36.0f, __fadd_rn(ori, PI_F));
    const float q0  = __fmul_rn(num, INV_TWOPI);
    const float e   = __fmaf_rn(-TWOPI_F, q0, num);
    const float o   = __fmaf_rn(e, INV_TWOPI, q0);
    const float bo = floorf(o);
    const float w  = __fmul_rn(__fsub_rn(1.0f, __fsub_rn(o, bo)), mag);
    int ib = (int)bo;
    if (ib >= NB) ib -= NB;       // only o==36 wraps (ori==+pi)
    atomicAdd(&h[ib], w);
}

__global__ __launch_bounds__(THREADS)
void orient_kernel(const float* __restrict__ x,
                   const float* __restrict__ gk,
                   float* __restrict__ out, int B) {
    __shared__ float hist[WPB * PPW][NB];

    const int warp = threadIdx.x >> 5;
    const int lane = threadIdx.x & 31;
    const int p    = lane >> 3;          // patch within warp (0..3)
    const int s    = lane & 7;           // 4-col strip (cols 4s..4s+3)
    const int b    = (blockIdx.x * WPB + warp) * PPW + p;
    if (b >= B) return;                  // warp-independent: no block syncs

    float* __restrict__ h = hist[warp * PPW + p];
    // Each warp zeros its own 4 histograms (144 floats) -> warp-local sync only.
    {
        float* hw = hist[warp * PPW];
        #pragma unroll
        for (int i = lane; i < PPW * NB; i += 32) hw[i] = 0.0f;
    }
    __syncwarp();

    const float4* px = reinterpret_cast<const float4*>(x + (size_t)b * (PS * PS)) + s;
    const float4* pg = reinterpret_cast<const float4*>(gk) + s;

    // Rolling float4 row buffer: up=row r-1(clamped), cur=row r, dn=row r+1(clamped)
    float4 cur = __ldg(px);              // row 0
    float4 dnv = __ldg(px + 8);          // row 1
    float4 upv = cur;                    // "row -1" = row 0 (replicate)
    float4 nxt = __ldg(px + 16);         // row 2 prefetch

    #pragma unroll 4
    for (int r = 0; r < PS; r++) {
        const float4 g = __ldg(pg + r * 8);

        // Horizontal strip-edge neighbors. Patch border (s==0/s==7): replicate.
        const float li = __shfl_up_sync(0xffffffffu, cur.w, 1);
        const float ri = __shfl_down_sync(0xffffffffu, cur.x, 1);
        const float lft0 = (s == 0) ? cur.x : li;   // left of col 4s
        const float rgt3 = (s == 7) ? cur.w : ri;   // right of col 4s+3

        pixel(lft0,  cur.y, upv.x, dnv.x, g.x, h);
        pixel(cur.x, cur.z, upv.y, dnv.y, g.y, h);
        pixel(cur.y, cur.w, upv.z, dnv.z, g.z, h);
        pixel(cur.z, rgt3,  upv.w, dnv.w, g.w, h);

        // Rotate; prefetch row r+3 (clamped). dn for last row = row 31 (replicate).
        upv = cur; cur = dnv; dnv = nxt;
        const int pr = (r + 3 < PS) ? (r + 3) : (PS - 1);
        nxt = __ldg(px + pr * 8);
    }
    __syncwarp();

    // Epilogue per 8-lane group: smooth (0.33,0.34,0.33) zero-padded,
    // first-max argmax, angle. Skipping /1024 is exactly argmax-equivalent.
    float bv = -1e30f;
    int bi = 0;
    #pragma unroll
    for (int k = 0; k < 5; k++) {
        const int i = s + k * 8;
        if (i < NB) {
            const float ctr = h[i];
            const float lft = (i > 0)      ? h[i - 1] : 0.0f;
            const float rgt = (i < NB - 1) ? h[i + 1] : 0.0f;
            const float sm = __fadd_rn(
                __fadd_rn(__fmul_rn(0.33f, lft), __fmul_rn(0.34f, ctr)),
                __fmul_rn(0.33f, rgt));
            if (sm > bv) { bv = sm; bi = i; }   // increasing i: '>' keeps first max
        }
    }
    #pragma unroll
    for (int off = 4; off > 0; off >>= 1) {     // reduce within 8-lane group
        const float ov = __shfl_xor_sync(0xffffffffu, bv, off);
        const int   oi = __shfl_xor_sync(0xffffffffu, bi, off);
        if (ov > bv || (ov == bv && oi < bi)) { bv = ov; bi = oi; }
    }
    if (s == 0) {
        // angle = -((2*pi*idx)/36 - pi), exact ref op order
        out[b] = -__fsub_rn(__fdiv_rn(__fmul_rn(TWOPI_F, (float)bi), 36.0f), PI_F);
    }
}

extern "C" void kernel_launch(void* const* d_in, const int* in_sizes, int n_in,
                              void* d_out, int out_size) {
    const float* x  = (const float*)d_in[0];
    const float* gk = (const float*)d_in[1];
    float* out = (float*)d_out;
    const int B = in_sizes[0] / (PS * PS);
    const int patches_per_block = WPB * PPW;
    const int grid = (B + patches_per_block - 1) / patches_per_block;
    orient_kernel<<<grid, THREADS>>>(x, gk, out, B);
}

// round 11
// speedup vs baseline: 1.2915x; 1.0190x over previous
#include <cuda_runtime.h>
#include <cstdint>

#define PS 32
#define NB 36
#define WPB 8                     // warps per block
#define PPW 4                     // patches per warp (8 lanes each)
#define THREADS (WPB * 32)

// fp32 constants exactly as XLA materializes them
#define PI_F     3.14159274101257324219f   // (float)pi
#define TWOPI_F  6.28318548202514648438f   // (float)(2*pi)
#define INV_TWOPI (1.0f / TWOPI_F)         // compile-time RN reciprocal

// One pixel: exact reference fp32 op order (no fma contraction).
__device__ __forceinline__ void pixel(float lft, float rgt, float up, float dn,
                                      float g, float* __restrict__ h) {
    const float gx = __fmul_rn(0.5f, __fsub_rn(lft, rgt));
    const float gy = __fmul_rn(0.5f, __fsub_rn(up, dn));
    const float s2 = __fadd_rn(__fadd_rn(__fmul_rn(gx, gx), __fmul_rn(gy, gy)), 1e-10f);
    const float mag = __fmul_rn(sqrtf(s2), g);
    const float ori = atan2f(gy, gx);
    // o = (36*(ori+pi))/(2pi), correctly-rounded constant division (Markstein)
    const float num = __fmul_rn(36.0f, __fadd_rn(ori, PI_F));
    const float q0  = __fmul_rn(num, INV_TWOPI);
    const float e   = __fmaf_rn(-TWOPI_F, q0, num);
    const float o   = __fmaf_rn(e, INV_TWOPI, q0);
    const float bo = floorf(o);
    const float w  = __fmul_rn(__fsub_rn(1.0f, __fsub_rn(o, bo)), mag);
    int ib = (int)bo;
    if (ib >= NB) ib -= NB;       // only o==36 wraps (ori==+pi)
    atomicAdd(&h[ib], w);
}

__global__ __launch_bounds__(THREADS, 6)   // cap regs ~40 -> 48 warps/SM
void orient_kernel(const float* __restrict__ x,
                   const float* __restrict__ gk,
                   float* __restrict__ out, int B) {
    __shared__ float hist[WPB * PPW][NB];

    const int warp = threadIdx.x >> 5;
    const int lane = threadIdx.x & 31;
    const int p    = lane >> 3;          // patch within warp (0..3)
    const int s    = lane & 7;           // 4-col strip (cols 4s..4s+3)
    const int b    = (blockIdx.x * WPB + warp) * PPW + p;
    if (b >= B) return;                  // warp-independent: no block syncs

    float* __restrict__ h = hist[warp * PPW + p];
    // Each warp zeros its own 4 histograms (144 floats) -> warp-local sync only.
    {
        float* hw = hist[warp * PPW];
        #pragma unroll
        for (int i = lane; i < PPW * NB; i += 32) hw[i] = 0.0f;
    }
    __syncwarp();

    const float4* px = reinterpret_cast<const float4*>(x + (size_t)b * (PS * PS)) + s;
    const float4* pg = reinterpret_cast<const float4*>(gk) + s;

    // Rolling float4 row buffer: upv=row r-1(clamped), cur=row r, dnv=row r+1(clamped)
    float4 cur = __ldg(px);              // row 0
    float4 dnv = __ldg(px + 8);          // row 1
    float4 upv = cur;                    // "row -1" = row 0 (replicate)

    #pragma unroll 4
    for (int r = 0; r < PS; r++) {
        const float4 g = __ldg(pg + r * 8);

        // Horizontal strip-edge neighbors. Patch border (s==0/s==7): replicate.
        const float li = __shfl_up_sync(0xffffffffu, cur.w, 1);
        const float ri = __shfl_down_sync(0xffffffffu, cur.x, 1);
        const float lft0 = (s == 0) ? cur.x : li;   // left of col 4s
        const float rgt3 = (s == 7) ? cur.w : ri;   // right of col 4s+3

        pixel(lft0,  cur.y, upv.x, dnv.x, g.x, h);
        pixel(cur.x, cur.z, upv.y, dnv.y, g.y, h);
        pixel(cur.y, cur.w, upv.z, dnv.z, g.z, h);
        pixel(cur.z, rgt3,  upv.w, dnv.w, g.w, h);

        // Rotate; load row r+2 (clamped) for the next iteration.
        upv = cur; cur = dnv;
        const int pr = (r + 2 < PS) ? (r + 2) : (PS - 1);
        dnv = __ldg(px + pr * 8);
    }
    __syncwarp();

    // Epilogue per 8-lane group: smooth (0.33,0.34,0.33) zero-padded,
    // first-max argmax, angle. Skipping /1024 is exactly argmax-equivalent.
    float bv = -1e30f;
    int bi = 0;
    #pragma unroll
    for (int k = 0; k < 5; k++) {
        const int i = s + k * 8;
        if (i < NB) {
            const float ctr = h[i];
            const float lft = (i > 0)      ? h[i - 1] : 0.0f;
            const float rgt = (i < NB - 1) ? h[i + 1] : 0.0f;
            const float sm = __fadd_rn(
                __fadd_rn(__fmul_rn(0.33f, lft), __fmul_rn(0.34f, ctr)),
                __fmul_rn(0.33f, rgt));
            if (sm > bv) { bv = sm; bi = i; }   // increasing i: '>' keeps first max
        }
    }
    #pragma unroll
    for (int off = 4; off > 0; off >>= 1) {     // reduce within 8-lane group
        const float ov = __shfl_xor_sync(0xffffffffu, bv, off);
        const int   oi = __shfl_xor_sync(0xffffffffu, bi, off);
        if (ov > bv || (ov == bv && oi < bi)) { bv = ov; bi = oi; }
    }
    if (s == 0) {
        // angle = -((2*pi*idx)/36 - pi), exact ref op order
        out[b] = -__fsub_rn(__fdiv_rn(__fmul_rn(TWOPI_F, (float)bi), 36.0f), PI_F);
    }
}

extern "C" void kernel_launch(void* const* d_in, const int* in_sizes, int n_in,
                              void* d_out, int out_size) {
    const float* x  = (const float*)d_in[0];
    const float* gk = (const float*)d_in[1];
    float* out = (float*)d_out;
    const int B = in_sizes[0] / (PS * PS);
    const int patches_per_block = WPB * PPW;
    const int grid = (B + patches_per_block - 1) / patches_per_block;
    orient_kernel<<<grid, THREADS>>>(x, gk, out, B);
}

// round 12
// speedup vs baseline: 1.3006x; 1.0070x over previous
#include <cuda_runtime.h>
#include <cstdint>

#define PS 32
#define NB 36
#define WPB 8                     // warps per block
#define PPW 4                     // patches per warp (8 lanes each)
#define THREADS (WPB * 32)

// fp32 constants exactly as XLA materializes them
#define PI_F     3.14159274101257324219f   // (float)pi
#define TWOPI_F  6.28318548202514648438f   // (float)(2*pi)
#define INV_TWOPI (1.0f / TWOPI_F)         // compile-time RN reciprocal

// One pixel: exact reference fp32 op order (no fma contraction).
__device__ __forceinline__ void pixel(float lft, float rgt, float up, float dn,
                                      float g, float* __restrict__ h) {
    const float gx = __fmul_rn(0.5f, __fsub_rn(lft, rgt));
    const float gy = __fmul_rn(0.5f, __fsub_rn(up, dn));
    const float s2 = __fadd_rn(__fadd_rn(__fmul_rn(gx, gx), __fmul_rn(gy, gy)), 1e-10f);
    const float mag = __fmul_rn(sqrtf(s2), g);
    const float ori = atan2f(gy, gx);
    // o = (36*(ori+pi))/(2pi), correctly-rounded constant division (Markstein)
    const float num = __fmul_rn(36.0f, __fadd_rn(ori, PI_F));
    const float q0  = __fmul_rn(num, INV_TWOPI);
    const float e   = __fmaf_rn(-TWOPI_F, q0, num);
    const float o   = __fmaf_rn(e, INV_TWOPI, q0);
    const float bo = floorf(o);
    const float w  = __fmul_rn(__fsub_rn(1.0f, __fsub_rn(o, bo)), mag);
    int ib = (int)bo;
    if (ib >= NB) ib -= NB;       // only o==36 wraps (ori==+pi)
    atomicAdd(&h[ib], w);
}

__global__ __launch_bounds__(THREADS, 7)   // cap regs ~36 -> 56 warps/SM
void orient_kernel(const float* __restrict__ x,
                   const float* __restrict__ gk,
                   float* __restrict__ out, int B) {
    __shared__ float hist[WPB * PPW][NB];

    const int warp = threadIdx.x >> 5;
    const int lane = threadIdx.x & 31;
    const int p    = lane >> 3;          // patch within warp (0..3)
    const int s    = lane & 7;           // 4-col strip (cols 4s..4s+3)
    const int b    = (blockIdx.x * WPB + warp) * PPW + p;
    if (b >= B) return;                  // warp-independent: no block syncs

    float* __restrict__ h = hist[warp * PPW + p];
    // Each warp zeros its own 4 histograms (144 floats) -> warp-local sync only.
    {
        float* hw = hist[warp * PPW];
        #pragma unroll
        for (int i = lane; i < PPW * NB; i += 32) hw[i] = 0.0f;
    }
    __syncwarp();

    const float4* px = reinterpret_cast<const float4*>(x + (size_t)b * (PS * PS)) + s;
    const float4* pg = reinterpret_cast<const float4*>(gk) + s;

    // Rolling float4 row buffer: upv=row r-1(clamped), cur=row r, dnv=row r+1(clamped)
    float4 cur = __ldg(px);              // row 0
    float4 dnv = __ldg(px + 8);          // row 1
    float4 upv = cur;                    // "row -1" = row 0 (replicate)

    #pragma unroll 4
    for (int r = 0; r < PS; r++) {
        const float4 g = __ldg(pg + r * 8);

        // Horizontal strip-edge neighbors. Patch border (s==0/s==7): replicate.
        const float li = __shfl_up_sync(0xffffffffu, cur.w, 1);
        const float ri = __shfl_down_sync(0xffffffffu, cur.x, 1);
        const float lft0 = (s == 0) ? cur.x : li;   // left of col 4s
        const float rgt3 = (s == 7) ? cur.w : ri;   // right of col 4s+3

        pixel(lft0,  cur.y, upv.x, dnv.x, g.x, h);
        pixel(cur.x, cur.z, upv.y, dnv.y, g.y, h);
        pixel(cur.y, cur.w, upv.z, dnv.z, g.z, h);
        pixel(cur.z, rgt3,  upv.w, dnv.w, g.w, h);

        // Rotate; load row r+2 (clamped) for the next iteration.
        upv = cur; cur = dnv;
        const int pr = (r + 2 < PS) ? (r + 2) : (PS - 1);
        dnv = __ldg(px + pr * 8);
    }
    __syncwarp();

    // Epilogue per 8-lane group: smooth (0.33,0.34,0.33) zero-padded,
    // first-max argmax, angle. Skipping /1024 is exactly argmax-equivalent.
    float bv = -1e30f;
    int bi = 0;
    #pragma unroll
    for (int k = 0; k < 5; k++) {
        const int i = s + k * 8;
        if (i < NB) {
            const float ctr = h[i];
            const float lft = (i > 0)      ? h[i - 1] : 0.0f;
            const float rgt = (i < NB - 1) ? h[i + 1] : 0.0f;
            const float sm = __fadd_rn(
                __fadd_rn(__fmul_rn(0.33f, lft), __fmul_rn(0.34f, ctr)),
                __fmul_rn(0.33f, rgt));
            if (sm > bv) { bv = sm; bi = i; }   // increasing i: '>' keeps first max
        }
    }
    #pragma unroll
    for (int off = 4; off > 0; off >>= 1) {     // reduce within 8-lane group
        const float ov = __shfl_xor_sync(0xffffffffu, bv, off);
        const int   oi = __shfl_xor_sync(0xffffffffu, bi, off);
        if (ov > bv || (ov == bv && oi < bi)) { bv = ov; bi = oi; }
    }
    if (s == 0) {
        // angle = -((2*pi*idx)/36 - pi), exact ref op order
        out[b] = -__fsub_rn(__fdiv_rn(__fmul_rn(TWOPI_F, (float)bi), 36.0f), PI_F);
    }
}

extern "C" void kernel_launch(void* const* d_in, const int* in_sizes, int n_in,
                              void* d_out, int out_size) {
    const float* x  = (const float*)d_in[0];
    const float* gk = (const float*)d_in[1];
    float* out = (float*)d_out;
    const int B = in_sizes[0] / (PS * PS);
    const int patches_per_block = WPB * PPW;
    const int grid = (B + patches_per_block - 1) / patches_per_block;
    orient_kernel<<<grid, THREADS>>>(x, gk, out, B);
}

// round 13
// speedup vs baseline: 1.3286x; 1.0216x over previous
#include <cuda_runtime.h>
#include <cstdint>

#define PS 32
#define NB 36
#define WPB 4                     // warps per block (128-thread CTAs)
#define PPW 4                     // patches per warp (8 lanes each)
#define THREADS (WPB * 32)

// fp32 constants exactly as XLA materializes them
#define PI_F     3.14159274101257324219f   // (float)pi
#define TWOPI_F  6.28318548202514648438f   // (float)(2*pi)
#define INV_TWOPI (1.0f / TWOPI_F)         // compile-time RN reciprocal

// One pixel: exact reference fp32 op order (no fma contraction).
__device__ __forceinline__ void pixel(float lft, float rgt, float up, float dn,
                                      float g, float* __restrict__ h) {
    const float gx = __fmul_rn(0.5f, __fsub_rn(lft, rgt));
    const float gy = __fmul_rn(0.5f, __fsub_rn(up, dn));
    const float s2 = __fadd_rn(__fadd_rn(__fmul_rn(gx, gx), __fmul_rn(gy, gy)), 1e-10f);
    const float mag = __fmul_rn(sqrtf(s2), g);
    const float ori = atan2f(gy, gx);
    // o = (36*(ori+pi))/(2pi), correctly-rounded constant division (Markstein)
    const float num = __fmul_rn(36.0f, __fadd_rn(ori, PI_F));
    const float q0  = __fmul_rn(num, INV_TWOPI);
    const float e   = __fmaf_rn(-TWOPI_F, q0, num);
    const float o   = __fmaf_rn(e, INV_TWOPI, q0);
    const float bo = floorf(o);
    const float w  = __fmul_rn(__fsub_rn(1.0f, __fsub_rn(o, bo)), mag);
    int ib = (int)bo;
    if (ib >= NB) ib -= NB;       // only o==36 wraps (ori==+pi)
    atomicAdd(&h[ib], w);
}

__global__ __launch_bounds__(THREADS, 16)  // 16 CTAs/SM -> 64 warps @ 32 regs
void orient_kernel(const float* __restrict__ x,
                   const float* __restrict__ gk,
                   float* __restrict__ out, int B) {
    __shared__ float hist[WPB * PPW][NB];

    const int warp = threadIdx.x >> 5;
    const int lane = threadIdx.x & 31;
    const int p    = lane >> 3;          // patch within warp (0..3)
    const int s    = lane & 7;           // 4-col strip (cols 4s..4s+3)
    const int b    = (blockIdx.x * WPB + warp) * PPW + p;
    if (b >= B) return;                  // warp-independent: no block syncs

    float* __restrict__ h = hist[warp * PPW + p];
    // Each warp zeros its own 4 histograms (144 floats) -> warp-local sync only.
    {
        float* hw = hist[warp * PPW];
        #pragma unroll
        for (int i = lane; i < PPW * NB; i += 32) hw[i] = 0.0f;
    }
    __syncwarp();

    const float4* px = reinterpret_cast<const float4*>(x + (size_t)b * (PS * PS)) + s;
    const float4* pg = reinterpret_cast<const float4*>(gk) + s;

    // Rolling float4 row buffer: upv=row r-1(clamped), cur=row r, dnv=row r+1(clamped)
    float4 cur = __ldg(px);              // row 0
    float4 dnv = __ldg(px + 8);          // row 1
    float4 upv = cur;                    // "row -1" = row 0 (replicate)

    #pragma unroll 4
    for (int r = 0; r < PS; r++) {
        const float4 g = __ldg(pg + r * 8);

        // Horizontal strip-edge neighbors. Patch border (s==0/s==7): replicate.
        const float li = __shfl_up_sync(0xffffffffu, cur.w, 1);
        const float ri = __shfl_down_sync(0xffffffffu, cur.x, 1);
        const float lft0 = (s == 0) ? cur.x : li;   // left of col 4s
        const float rgt3 = (s == 7) ? cur.w : ri;   // right of col 4s+3

        pixel(lft0,  cur.y, upv.x, dnv.x, g.x, h);
        pixel(cur.x, cur.z, upv.y, dnv.y, g.y, h);
        pixel(cur.y, cur.w, upv.z, dnv.z, g.z, h);
        pixel(cur.z, rgt3,  upv.w, dnv.w, g.w, h);

        // Rotate; load row r+2 (clamped) for the next iteration.
        upv = cur; cur = dnv;
        const int pr = (r + 2 < PS) ? (r + 2) : (PS - 1);
        dnv = __ldg(px + pr * 8);
    }
    __syncwarp();

    // Epilogue per 8-lane group: smooth (0.33,0.34,0.33) zero-padded,
    // first-max argmax, angle. Skipping /1024 is exactly argmax-equivalent.
    float bv = -1e30f;
    int bi = 0;
    #pragma unroll
    for (int k = 0; k < 5; k++) {
        const int i = s + k * 8;
        if (i < NB) {
            const float ctr = h[i];
            const float lft = (i > 0)      ? h[i - 1] : 0.0f;
            const float rgt = (i < NB - 1) ? h[i + 1] : 0.0f;
            const float sm = __fadd_rn(
                __fadd_rn(__fmul_rn(0.33f, lft), __fmul_rn(0.34f, ctr)),
                __fmul_rn(0.33f, rgt));
            if (sm > bv) { bv = sm; bi = i; }   // increasing i: '>' keeps first max
        }
    }
    #pragma unroll
    for (int off = 4; off > 0; off >>= 1) {     // reduce within 8-lane group
        const float ov = __shfl_xor_sync(0xffffffffu, bv, off);
        const int   oi = __shfl_xor_sync(0xffffffffu, bi, off);
        if (ov > bv || (ov == bv && oi < bi)) { bv = ov; bi = oi; }
    }
    if (s == 0) {
        // angle = -((2*pi*idx)/36 - pi), exact ref op order
        out[b] = -__fsub_rn(__fdiv_rn(__fmul_rn(TWOPI_F, (float)bi), 36.0f), PI_F);
    }
}

extern "C" void kernel_launch(void* const* d_in, const int* in_sizes, int n_in,
                              void* d_out, int out_size) {
    const float* x  = (const float*)d_in[0];
    const float* gk = (const float*)d_in[1];
    float* out = (float*)d_out;
    const int B = in_sizes[0] / (PS * PS);
    const int patches_per_block = WPB * PPW;
    const int grid = (B + patches_per_block - 1) / patches_per_block;
    orient_kernel<<<grid, THREADS>>>(x, gk, out, B);
}